// round 4
// baseline (speedup 1.0000x reference)
#include <cuda_runtime.h>

#define BB 16
#define TT 2048
#define FF 512
#define SPB 4   // segments per k_pool block

// Scratch (allocation-free rule: device globals)
__device__ float g_wt[BB * TT];      // gate weights
__device__ int   g_vlist[BB * TT];   // packed valley positions per batch
__device__ int   g_nv[BB];           // number of valleys k per batch

// ---------------------------------------------------------------------------
// Kernel 1: wt = sigmoid(x·w + b). One warp per 8 rows (2 groups of 4).
// w held in registers (loaded once per warp); x loads dominate.
// ---------------------------------------------------------------------------
__global__ void k_gate(const float* __restrict__ x,
                       const float* __restrict__ w,
                       const float* __restrict__ bias) {
    int lane = threadIdx.x & 31;
    int gw   = blockIdx.x * (blockDim.x >> 5) + (threadIdx.x >> 5);
    int row0 = gw * 8;
    if (row0 >= BB * TT) return;

    const float4* wr = (const float4*)w;
    float4 c0 = wr[lane];
    float4 c1 = wr[lane + 32];
    float4 c2 = wr[lane + 64];
    float4 c3 = wr[lane + 96];
    float  bz = bias[0];

#pragma unroll
    for (int g = 0; g < 2; g++) {
        int r = row0 + g * 4;
        const float4* p0 = (const float4*)(x + (size_t)r * FF);
        const float4* p1 = p0 + FF / 4;
        const float4* p2 = p1 + FF / 4;
        const float4* p3 = p2 + FF / 4;

        float s0 = 0.f, s1 = 0.f, s2 = 0.f, s3 = 0.f;
#pragma unroll
        for (int j = 0; j < 4; j++) {
            int idx = lane + 32 * j;
            float4 cj = (j == 0) ? c0 : (j == 1) ? c1 : (j == 2) ? c2 : c3;
            float4 a0 = p0[idx];
            float4 a1 = p1[idx];
            float4 a2 = p2[idx];
            float4 a3 = p3[idx];
            s0 += a0.x * cj.x + a0.y * cj.y + a0.z * cj.z + a0.w * cj.w;
            s1 += a1.x * cj.x + a1.y * cj.y + a1.z * cj.z + a1.w * cj.w;
            s2 += a2.x * cj.x + a2.y * cj.y + a2.z * cj.z + a2.w * cj.w;
            s3 += a3.x * cj.x + a3.y * cj.y + a3.z * cj.z + a3.w * cj.w;
        }
#pragma unroll
        for (int o = 16; o; o >>= 1) {
            s0 += __shfl_down_sync(0xffffffffu, s0, o);
            s1 += __shfl_down_sync(0xffffffffu, s1, o);
            s2 += __shfl_down_sync(0xffffffffu, s2, o);
            s3 += __shfl_down_sync(0xffffffffu, s3, o);
        }
        if (lane == 0) {
            float4 r4;
            r4.x = 1.f / (1.f + expf(-(s0 + bz)));
            r4.y = 1.f / (1.f + expf(-(s1 + bz)));
            r4.z = 1.f / (1.f + expf(-(s2 + bz)));
            r4.w = 1.f / (1.f + expf(-(s3 + bz)));
            *(float4*)(g_wt + r) = r4;
        }
    }
}

// ---------------------------------------------------------------------------
// Kernel 2: per batch, strict local minima of wt, left-packed positions.
// Warp-shuffle scan instead of the O(log n) full-block ladder.
// ---------------------------------------------------------------------------
__global__ void k_valleys() {
    __shared__ float sw[TT];
    __shared__ int   wsum[9];

    int b    = blockIdx.x;
    int tid  = threadIdx.x;                // 256 threads
    int lane = tid & 31;
    int wid  = tid >> 5;

    for (int t = tid; t < TT; t += 256) sw[t] = g_wt[b * TT + t];
    __syncthreads();

    const int PER = TT / 256;              // 8 consecutive t per thread
    int base = tid * PER;
    unsigned char fl[PER];
    int c = 0;
#pragma unroll
    for (int j = 0; j < PER; j++) {
        int   t   = base + j;
        float wtt = sw[t];
        float bef = (t == 0)      ? 0.f : sw[t - 1];
        float aft = (t == TT - 1) ? 0.f : sw[t + 1];
        bool  v   = (wtt < bef) && (wtt < aft);
        fl[j] = v ? 1 : 0;
        c += v ? 1 : 0;
    }

    // warp-inclusive scan of per-thread counts
    int incl = c;
#pragma unroll
    for (int o = 1; o < 32; o <<= 1) {
        int v = __shfl_up_sync(0xffffffffu, incl, o);
        if (lane >= o) incl += v;
    }
    if (lane == 31) wsum[wid] = incl;
    __syncthreads();
    if (tid == 0) {
        int run = 0;
#pragma unroll
        for (int j = 0; j < 8; j++) { int t = wsum[j]; wsum[j] = run; run += t; }
        wsum[8] = run;
        g_nv[b] = run;
    }
    __syncthreads();

    int pos = wsum[wid] + incl - c;        // exclusive prefix for this thread
#pragma unroll
    for (int j = 0; j < PER; j++) {
        if (fl[j]) g_vlist[b * TT + (pos++)] = base + j;
    }
}

// ---------------------------------------------------------------------------
// Kernel 3: streaming segment pooling; SPB consecutive segments per block,
// each x row read once, 2-row overlap carried in registers (ascending sum
// order preserved). Streaming stores keep x resident in L2.
// ---------------------------------------------------------------------------
__global__ void k_pool(const float* __restrict__ x,
                       const int* __restrict__ seq_len,
                       float* __restrict__ out,
                       int write_mask) {
    int b   = blockIdx.y;
    int j   = blockIdx.x;
    int tid = threadIdx.x;                 // 128 threads, one float4 column each
    int k = g_nv[b];
    int n = k + 1;
    int i0 = j * SPB;

    float4 z4 = make_float4(0.f, 0.f, 0.f, 0.f);
    for (int i = max(i0, n); i < i0 + SPB; i++)
        __stcs((float4*)(out + ((size_t)b * TT + i) * FF) + tid, z4);

    if (i0 < n) {
        int iEnd = min(i0 + SPB, n);
        const float4* xb = (const float4*)(x + (size_t)b * TT * FF);
        const float*  wb = g_wt + b * TT;
        const int*    vb = g_vlist + b * TT;

        float4 carry = z4;
        float  dcarry = 0.f;
        bool   have = false;

        for (int i = i0; i < iEnd; i++) {
            int S = (i == 0) ? 0 : vb[i - 1];
            int E = (i < k) ? min(vb[i] + 2, TT) : TT;

            float4 acc;
            float  den;
            int t;
            if (have) { acc = carry; den = dcarry; t = S + 2; }
            else      { acc = z4;    den = 0.f;    t = S;     }

            int bodyEnd = E - 2;           // body: rows not in the next overlap
#pragma unroll 2
            for (; t < bodyEnd; t++) {
                float  wv = wb[t];
                float4 xv = xb[(size_t)t * (FF / 4) + tid];
                acc.x += wv * xv.x;  acc.y += wv * xv.y;
                acc.z += wv * xv.z;  acc.w += wv * xv.w;
                den += wv;
            }
            float4 c2 = z4;
            float  d2 = 0.f;
            for (; t < E; t++) {           // overlap rows [E-2, E)
                float  wv = wb[t];
                float4 xv = xb[(size_t)t * (FF / 4) + tid];
                acc.x += wv * xv.x;  acc.y += wv * xv.y;
                acc.z += wv * xv.z;  acc.w += wv * xv.w;
                den += wv;
                c2.x += wv * xv.x;  c2.y += wv * xv.y;
                c2.z += wv * xv.z;  c2.w += wv * xv.w;
                d2 += wv;
            }
            carry = c2; dcarry = d2; have = true;

            float inv = 1.f / fmaxf(den, 1e-6f);
            float4 r;
            r.x = acc.x * inv;  r.y = acc.y * inv;
            r.z = acc.z * inv;  r.w = acc.w * inv;
            __stcs((float4*)(out + ((size_t)b * TT + i) * FF) + tid, r);
        }
    }

    if (write_mask && tid < SPB) {
        int i = i0 + tid;
        int mc = 0;
#pragma unroll
        for (int bb = 0; bb < BB; bb++) {
            int c = g_nv[bb] + 1;
            if (c > mc) mc = c;
        }
        int len  = min(seq_len[b], TT);
        int len0 = min(seq_len[0], TT);
        int nl   = (int)((float)len / (float)len0 * (float)mc);
        float* m = out + (size_t)BB * TT * FF;
        __stcs(&m[(size_t)b * TT + i], (i < nl) ? 1.f : 0.f);
    }
}

// ---------------------------------------------------------------------------
extern "C" void kernel_launch(void* const* d_in, const int* in_sizes, int n_in,
                              void* d_out, int out_size) {
    const float* x    = (const float*)d_in[0];   // [B,T,F] f32
    const float* w    = (const float*)d_in[1];   // [F,1]  f32
    const float* bias = (const float*)d_in[2];   // [1]    f32
    const int*   seq  = (const int*)d_in[3];     // [B]    i32
    float* out = (float*)d_out;

    int write_mask = (out_size >= BB * TT * FF + BB * TT) ? 1 : 0;

    k_gate<<<(BB * TT) / (8 * 8), 256>>>(x, w, bias);   // 512 blocks, 8 rows/warp
    k_valleys<<<BB, 256>>>();
    dim3 grid(TT / SPB, BB);
    k_pool<<<grid, 128>>>(x, seq, out, write_mask);
}